// round 1
// baseline (speedup 1.0000x reference)
#include <cuda_runtime.h>

#define L_SEQ  2048
#define NB     4
#define NHEAD  16
#define HDIM   64
#define DMODEL 1024

// Scratch for Q/K/V in [B, H, L, Dh] layout (32 MB each; static device = allowed)
__device__ float g_q[(size_t)NB * NHEAD * L_SEQ * HDIM];
__device__ float g_k[(size_t)NB * NHEAD * L_SEQ * HDIM];
__device__ float g_v[(size_t)NB * NHEAD * L_SEQ * HDIM];

// ---------------------------------------------------------------------------
// QKV projection: out[m, n] = sum_k x[m,k] * w[n,k] + b[n]
// M = 8192 (B*L), N = 1024 (H*Dh), K = 1024. grid.z selects q/k/v.
// Output written directly in [B, H, L, Dh] layout (N-tile == head since BN=64).
// ---------------------------------------------------------------------------
__global__ __launch_bounds__(256) void qkv_gemm_kernel(
    const float* __restrict__ x,
    const float* __restrict__ wq, const float* __restrict__ bq,
    const float* __restrict__ wk, const float* __restrict__ bk,
    const float* __restrict__ wv, const float* __restrict__ bv)
{
    __shared__ float sXt[32][68];   // [k][m]  (transposed tile)
    __shared__ float sWt[32][68];   // [k][n]

    const float* w;
    const float* bias;
    float* dst;
    if (blockIdx.z == 0)      { w = wq; bias = bq; dst = g_q; }
    else if (blockIdx.z == 1) { w = wk; bias = bk; dst = g_k; }
    else                      { w = wv; bias = bv; dst = g_v; }

    const int tid = threadIdx.x;
    const int tx = tid & 15;        // col group (n)
    const int ty = tid >> 4;        // row group (m)
    const int m0 = blockIdx.x * 64;
    const int n0 = blockIdx.y * 64;

    float acc[4][4] = {};

    for (int k0 = 0; k0 < DMODEL; k0 += 32) {
        // load + transpose tiles: 64 rows x 32 k, 512 float4 / 256 threads
        #pragma unroll
        for (int i = 0; i < 2; i++) {
            int idx = tid + i * 256;
            int row = idx >> 3;     // 0..63
            int kq  = idx & 7;      // float4 index along k
            float4 vx = *(const float4*)&x[(size_t)(m0 + row) * DMODEL + k0 + kq * 4];
            sXt[kq * 4 + 0][row] = vx.x;
            sXt[kq * 4 + 1][row] = vx.y;
            sXt[kq * 4 + 2][row] = vx.z;
            sXt[kq * 4 + 3][row] = vx.w;
            float4 vw = *(const float4*)&w[(size_t)(n0 + row) * DMODEL + k0 + kq * 4];
            sWt[kq * 4 + 0][row] = vw.x;
            sWt[kq * 4 + 1][row] = vw.y;
            sWt[kq * 4 + 2][row] = vw.z;
            sWt[kq * 4 + 3][row] = vw.w;
        }
        __syncthreads();

        #pragma unroll 8
        for (int k = 0; k < 32; k++) {
            float a[4], b[4];
            *(float4*)a = *(const float4*)&sXt[k][ty * 4];
            *(float4*)b = *(const float4*)&sWt[k][tx * 4];
            #pragma unroll
            for (int i = 0; i < 4; i++)
                #pragma unroll
                for (int j = 0; j < 4; j++)
                    acc[i][j] += a[i] * b[j];
        }
        __syncthreads();
    }

    float bia[4];
    *(float4*)bia = *(const float4*)&bias[n0 + tx * 4];

    const int bi = m0 / L_SEQ;      // batch (tile fully inside one batch)
    const int l0 = m0 % L_SEQ;
    const int h  = blockIdx.y;      // BN == HDIM so N-tile index == head

    #pragma unroll
    for (int i = 0; i < 4; i++) {
        int l = l0 + ty * 4 + i;
        float4 r;
        r.x = acc[i][0] + bia[0];
        r.y = acc[i][1] + bia[1];
        r.z = acc[i][2] + bia[2];
        r.w = acc[i][3] + bia[3];
        *(float4*)&dst[(((size_t)(bi * NHEAD + h)) * L_SEQ + l) * HDIM + tx * 4] = r;
    }
}

// ---------------------------------------------------------------------------
// Flash attention: one CTA = one (b,h) head x 64 query rows.
// Iterates 32 key tiles of 64, online softmax, fp32.
// ---------------------------------------------------------------------------
__global__ __launch_bounds__(256) void attn_kernel(
    const float* __restrict__ mask, float* __restrict__ out)
{
    extern __shared__ float smem[];
    float (*sQt)[68] = (float(*)[68])(smem);                // [d][r]
    float (*sKt)[68] = (float(*)[68])(smem + 64 * 68);      // [d][c]
    float (*sV )[68] = (float(*)[68])(smem + 2 * 64 * 68);  // [c][d]
    float (*sP )[68] = (float(*)[68])(smem + 3 * 64 * 68);  // [r][c]

    const int tid = threadIdx.x;
    const int tx = tid & 15;        // col group (c or d)
    const int ty = tid >> 4;        // row group (r)
    const int rt = blockIdx.x;      // query row tile
    const int bh = blockIdx.y;      // b*16 + h
    const int bi = bh >> 4;
    const int h  = bh & 15;

    const float* Q    = g_q + ((size_t)bh * L_SEQ + rt * 64) * HDIM;
    const float* Kb   = g_k + (size_t)bh * L_SEQ * HDIM;
    const float* Vb   = g_v + (size_t)bh * L_SEQ * HDIM;
    const float* Mrow = mask + ((size_t)bi * L_SEQ + rt * 64) * L_SEQ;

    // load Q tile transposed: 4096 floats = 1024 float4
    #pragma unroll
    for (int i = 0; i < 4; i++) {
        int idx = tid + i * 256;
        int row = idx >> 4;         // 0..63
        int dq  = idx & 15;
        float4 v = *(const float4*)&Q[row * HDIM + dq * 4];
        sQt[dq * 4 + 0][row] = v.x;
        sQt[dq * 4 + 1][row] = v.y;
        sQt[dq * 4 + 2][row] = v.z;
        sQt[dq * 4 + 3][row] = v.w;
    }

    float mi[4], li[4], o[4][4];
    #pragma unroll
    for (int i = 0; i < 4; i++) {
        mi[i] = -1e30f;
        li[i] = 0.0f;
        #pragma unroll
        for (int j = 0; j < 4; j++) o[i][j] = 0.0f;
    }

    for (int kt = 0; kt < L_SEQ / 64; kt++) {
        const float* Kt = Kb + kt * 64 * HDIM;
        const float* Vt = Vb + kt * 64 * HDIM;

        #pragma unroll
        for (int i = 0; i < 4; i++) {
            int idx = tid + i * 256;
            int row = idx >> 4;
            int dq  = idx & 15;
            float4 v = *(const float4*)&Kt[row * HDIM + dq * 4];
            sKt[dq * 4 + 0][row] = v.x;
            sKt[dq * 4 + 1][row] = v.y;
            sKt[dq * 4 + 2][row] = v.z;
            sKt[dq * 4 + 3][row] = v.w;
            float4 u = *(const float4*)&Vt[row * HDIM + dq * 4];
            *(float4*)&sV[row][dq * 4] = u;
        }
        __syncthreads();

        // S = Q K^T  (outer product over d)
        float s[4][4] = {};
        #pragma unroll 8
        for (int d = 0; d < 64; d++) {
            float a[4], b[4];
            *(float4*)a = *(const float4*)&sQt[d][ty * 4];
            *(float4*)b = *(const float4*)&sKt[d][tx * 4];
            #pragma unroll
            for (int i = 0; i < 4; i++)
                #pragma unroll
                for (int j = 0; j < 4; j++)
                    s[i][j] += a[i] * b[j];
        }

        // scale + mask
        #pragma unroll
        for (int i = 0; i < 4; i++) {
            float mk[4];
            *(float4*)mk = *(const float4*)&Mrow[(size_t)(ty * 4 + i) * L_SEQ + kt * 64 + tx * 4];
            #pragma unroll
            for (int j = 0; j < 4; j++)
                s[i][j] = s[i][j] * 0.125f + mk[j];
        }

        // online softmax update (row groups of 16 lanes)
        #pragma unroll
        for (int i = 0; i < 4; i++) {
            float mx = fmaxf(fmaxf(s[i][0], s[i][1]), fmaxf(s[i][2], s[i][3]));
            mx = fmaxf(mx, __shfl_xor_sync(0xffffffffu, mx, 8));
            mx = fmaxf(mx, __shfl_xor_sync(0xffffffffu, mx, 4));
            mx = fmaxf(mx, __shfl_xor_sync(0xffffffffu, mx, 2));
            mx = fmaxf(mx, __shfl_xor_sync(0xffffffffu, mx, 1));
            float mnew  = fmaxf(mi[i], mx);
            float alpha = __expf(mi[i] - mnew);
            mi[i] = mnew;
            float p[4];
            #pragma unroll
            for (int j = 0; j < 4; j++) p[j] = __expf(s[i][j] - mnew);
            float sum = p[0] + p[1] + p[2] + p[3];
            sum += __shfl_xor_sync(0xffffffffu, sum, 8);
            sum += __shfl_xor_sync(0xffffffffu, sum, 4);
            sum += __shfl_xor_sync(0xffffffffu, sum, 2);
            sum += __shfl_xor_sync(0xffffffffu, sum, 1);
            li[i] = li[i] * alpha + sum;
            #pragma unroll
            for (int j = 0; j < 4; j++) o[i][j] *= alpha;
            float4 pv = {p[0], p[1], p[2], p[3]};
            *(float4*)&sP[ty * 4 + i][tx * 4] = pv;
        }
        __syncthreads();

        // O += P V (outer product over c; a = column loads, b = float4 rows)
        #pragma unroll 4
        for (int c = 0; c < 64; c++) {
            float a0 = sP[ty * 4 + 0][c];
            float a1 = sP[ty * 4 + 1][c];
            float a2 = sP[ty * 4 + 2][c];
            float a3 = sP[ty * 4 + 3][c];
            float b[4];
            *(float4*)b = *(const float4*)&sV[c][tx * 4];
            #pragma unroll
            for (int j = 0; j < 4; j++) {
                o[0][j] += a0 * b[j];
                o[1][j] += a1 * b[j];
                o[2][j] += a2 * b[j];
                o[3][j] += a3 * b[j];
            }
        }
        __syncthreads();
    }

    // normalize + write out[b, l, h*64 + d]
    #pragma unroll
    for (int i = 0; i < 4; i++) {
        float inv = 1.0f / li[i];
        int l = rt * 64 + ty * 4 + i;
        float4 r;
        r.x = o[i][0] * inv;
        r.y = o[i][1] * inv;
        r.z = o[i][2] * inv;
        r.w = o[i][3] * inv;
        *(float4*)&out[((size_t)bi * L_SEQ + l) * DMODEL + h * HDIM + tx * 4] = r;
    }
}

// ---------------------------------------------------------------------------
extern "C" void kernel_launch(void* const* d_in, const int* in_sizes, int n_in,
                              void* d_out, int out_size)
{
    const float* x    = (const float*)d_in[0];
    const float* mask = (const float*)d_in[1];
    const float* wq   = (const float*)d_in[2];
    const float* bq   = (const float*)d_in[3];
    const float* wk   = (const float*)d_in[4];
    const float* bk   = (const float*)d_in[5];
    const float* wv   = (const float*)d_in[6];
    const float* bv   = (const float*)d_in[7];
    float* out = (float*)d_out;

    dim3 gg((NB * L_SEQ) / 64, DMODEL / 64, 3);
    qkv_gemm_kernel<<<gg, 256>>>(x, wq, bq, wk, bk, wv, bv);

    const int smem_attn = 4 * 64 * 68 * (int)sizeof(float);   // 69632 B
    cudaFuncSetAttribute(attn_kernel,
                         cudaFuncAttributeMaxDynamicSharedMemorySize, smem_attn);
    dim3 ga(L_SEQ / 64, NB * NHEAD);
    attn_kernel<<<ga, 256, smem_attn>>>(mask, out);
}

// round 6
// speedup vs baseline: 2.8123x; 2.8123x over previous
#include <cuda_runtime.h>
#include <cuda_bf16.h>

#define L_SEQ  2048
#define NB     4
#define NHEAD  16
#define HDIM   64
#define DMODEL 1024

// ---------------------------------------------------------------------------
// Device-global scratch (static allocations are allowed)
// ---------------------------------------------------------------------------
__device__ __nv_bfloat16 g_xh[8388608], g_xl[8388608];   // x split     [8192,1024]
__device__ __nv_bfloat16 g_wh[3145728], g_wl[3145728];   // wq|wk|wv    [3,1024,1024]
__device__ __nv_bfloat16 g_qh[8388608], g_ql[8388608];   // Q split     [64 bh][2048][64] (pre-scaled by 0.125)
__device__ __nv_bfloat16 g_kh[8388608], g_kl[8388608];   // K split     same layout
__device__ float         g_vv[8388608];                  // V fp32      same layout

// ---------------------------------------------------------------------------
// Helpers
// ---------------------------------------------------------------------------
__device__ __forceinline__ unsigned pack_bf16(float a, float b) {
    __nv_bfloat162 t = __floats2bfloat162_rn(a, b);
    return *(unsigned*)&t;
}
// split (a,b) into hi/lo bf16 pairs packed as u32
__device__ __forceinline__ void split2(float a, float b, unsigned &hi, unsigned &lo) {
    __nv_bfloat16 ah = __float2bfloat16(a);
    __nv_bfloat16 bh = __float2bfloat16(b);
    __nv_bfloat162 hv; hv.x = ah; hv.y = bh;
    hi = *(unsigned*)&hv;
    lo = pack_bf16(a - __bfloat162float(ah), b - __bfloat162float(bh));
}
__device__ __forceinline__ void mma16816(float c[4], const unsigned a[4],
                                         unsigned b0, unsigned b1) {
    asm volatile(
        "mma.sync.aligned.m16n8k16.row.col.f32.bf16.bf16.f32 "
        "{%0,%1,%2,%3}, {%4,%5,%6,%7}, {%8,%9}, {%0,%1,%2,%3};"
        : "+f"(c[0]), "+f"(c[1]), "+f"(c[2]), "+f"(c[3])
        : "r"(a[0]), "r"(a[1]), "r"(a[2]), "r"(a[3]), "r"(b0), "r"(b1));
}

// ---------------------------------------------------------------------------
// Split x and the three weight matrices into bf16 hi/lo (4-wide)
// id ranges: x [0,8388608) wq [.. ,9437184) wk [..,10485760) wv [..,11534336)
// ---------------------------------------------------------------------------
__global__ __launch_bounds__(256) void split_all(
    const float* __restrict__ x,  const float* __restrict__ wq,
    const float* __restrict__ wk, const float* __restrict__ wv)
{
    size_t i = ((size_t)blockIdx.x * 256 + threadIdx.x) * 4;
    const float* src; __nv_bfloat16 *dh, *dl; size_t off;
    if (i < 8388608)       { src = x;  dh = g_xh;           dl = g_xl;           off = i; }
    else if (i < 9437184)  { src = wq; dh = g_wh;           dl = g_wl;           off = i - 8388608; }
    else if (i < 10485760) { src = wk; dh = g_wh + 1048576; dl = g_wl + 1048576; off = i - 9437184; }
    else                   { src = wv; dh = g_wh + 2097152; dl = g_wl + 2097152; off = i - 10485760; }
    float4 v = *(const float4*)&src[off];
    __nv_bfloat16 h0 = __float2bfloat16(v.x), h1 = __float2bfloat16(v.y);
    __nv_bfloat16 h2 = __float2bfloat16(v.z), h3 = __float2bfloat16(v.w);
    uint2 ho, lo;
    { __nv_bfloat162 t0; t0.x = h0; t0.y = h1; ho.x = *(unsigned*)&t0;
      __nv_bfloat162 t1; t1.x = h2; t1.y = h3; ho.y = *(unsigned*)&t1; }
    lo.x = pack_bf16(v.x - __bfloat162float(h0), v.y - __bfloat162float(h1));
    lo.y = pack_bf16(v.z - __bfloat162float(h2), v.w - __bfloat162float(h3));
    *(uint2*)&dh[off] = ho;
    *(uint2*)&dl[off] = lo;
}

// ---------------------------------------------------------------------------
// QKV GEMM via mma.sync: out[m,n] = sum_k x[m,k] w[n,k] + b[n]
// CTA: 128 thr (4 warps), tile 64m x 64n, k-chunks of 64. grid (128,16,3).
// Q (z=0): scaled by 0.125, split -> g_qh/g_ql. K (z=1): split -> g_kh/g_kl.
// V (z=2): fp32 -> g_vv. Layout [bh][l][64].
// ---------------------------------------------------------------------------
__global__ __launch_bounds__(128) void qkv_kernel(
    const float* __restrict__ bq, const float* __restrict__ bk,
    const float* __restrict__ bv)
{
    __shared__ __nv_bfloat16 sxh[64 * 72], sxl[64 * 72];
    __shared__ __nv_bfloat16 swh[64 * 72], swl[64 * 72];

    const int z    = blockIdx.z;
    const int tid  = threadIdx.x;
    const int warp = tid >> 5;
    const int l    = tid & 31;
    const int m0   = blockIdx.x * 64;
    const int h    = blockIdx.y;
    const int n0   = h * 64;

    const __nv_bfloat16* wh = g_wh + (size_t)z * 1048576;
    const __nv_bfloat16* wl = g_wl + (size_t)z * 1048576;

    float acc[8][4] = {};

    for (int k0 = 0; k0 < DMODEL; k0 += 64) {
        if (k0) __syncthreads();
        #pragma unroll
        for (int i = 0; i < 4; i++) {
            int g = tid + i * 128;          // 512 granules of 16B per array
            int row = g >> 3, c8 = g & 7;
            *(uint4*)&sxh[row * 72 + c8 * 8] =
                *(const uint4*)&g_xh[(size_t)(m0 + row) * DMODEL + k0 + c8 * 8];
            *(uint4*)&sxl[row * 72 + c8 * 8] =
                *(const uint4*)&g_xl[(size_t)(m0 + row) * DMODEL + k0 + c8 * 8];
            *(uint4*)&swh[row * 72 + c8 * 8] =
                *(const uint4*)&wh[(size_t)(n0 + row) * DMODEL + k0 + c8 * 8];
            *(uint4*)&swl[row * 72 + c8 * 8] =
                *(const uint4*)&wl[(size_t)(n0 + row) * DMODEL + k0 + c8 * 8];
        }
        __syncthreads();

        #pragma unroll
        for (int ks = 0; ks < 4; ks++) {
            const int ar = warp * 16 + (l >> 2);
            const int ac = ks * 16 + (l & 3) * 2;
            unsigned ah[4], al[4];
            ah[0] = *(unsigned*)&sxh[ar * 72 + ac];
            ah[1] = *(unsigned*)&sxh[(ar + 8) * 72 + ac];
            ah[2] = *(unsigned*)&sxh[ar * 72 + ac + 8];
            ah[3] = *(unsigned*)&sxh[(ar + 8) * 72 + ac + 8];
            al[0] = *(unsigned*)&sxl[ar * 72 + ac];
            al[1] = *(unsigned*)&sxl[(ar + 8) * 72 + ac];
            al[2] = *(unsigned*)&sxl[ar * 72 + ac + 8];
            al[3] = *(unsigned*)&sxl[(ar + 8) * 72 + ac + 8];
            #pragma unroll
            for (int nt = 0; nt < 8; nt++) {
                const int br = nt * 8 + (l >> 2);
                unsigned b0h = *(unsigned*)&swh[br * 72 + ac];
                unsigned b1h = *(unsigned*)&swh[br * 72 + ac + 8];
                unsigned b0l = *(unsigned*)&swl[br * 72 + ac];
                unsigned b1l = *(unsigned*)&swl[br * 72 + ac + 8];
                mma16816(acc[nt], ah, b0h, b1h);
                mma16816(acc[nt], ah, b0l, b1l);
                mma16816(acc[nt], al, b0h, b1h);
            }
        }
    }

    // epilogue
    const float* bias = (z == 0) ? bq : (z == 1) ? bk : bv;
    const int r0 = m0 + warp * 16 + (l >> 2);   // global m of c0,c1
    const int c0 = (l & 3) * 2;
    const int bi = m0 >> 11;                    // batch
    const int lg = r0 & (L_SEQ - 1);            // l within batch
    const size_t bhbase = (size_t)(bi * NHEAD + h) * L_SEQ;

    #pragma unroll
    for (int nt = 0; nt < 8; nt++) {
        const int d = nt * 8 + c0;
        float2 b2 = *(const float2*)&bias[n0 + d];
        float v0 = acc[nt][0] + b2.x, v1 = acc[nt][1] + b2.y;   // row lg
        float v2 = acc[nt][2] + b2.x, v3 = acc[nt][3] + b2.y;   // row lg+8
        if (z == 2) {
            *(float2*)&g_vv[(bhbase + lg)     * HDIM + d] = make_float2(v0, v1);
            *(float2*)&g_vv[(bhbase + lg + 8) * HDIM + d] = make_float2(v2, v3);
        } else {
            if (z == 0) { v0 *= 0.125f; v1 *= 0.125f; v2 *= 0.125f; v3 *= 0.125f; }
            __nv_bfloat16* dh = (z == 0) ? g_qh : g_kh;
            __nv_bfloat16* dl = (z == 0) ? g_ql : g_kl;
            unsigned hi, lo;
            split2(v0, v1, hi, lo);
            *(unsigned*)&dh[(bhbase + lg) * HDIM + d] = hi;
            *(unsigned*)&dl[(bhbase + lg) * HDIM + d] = lo;
            split2(v2, v3, hi, lo);
            *(unsigned*)&dh[(bhbase + lg + 8) * HDIM + d] = hi;
            *(unsigned*)&dl[(bhbase + lg + 8) * HDIM + d] = lo;
        }
    }
}

// ---------------------------------------------------------------------------
// Flash attention via mma.sync. CTA: 256 thr (8 warps), 128 q-rows, K-tiles
// of 64. Warp w owns q rows [w*16, w*16+16). grid (16, 64).
// ---------------------------------------------------------------------------
__global__ __launch_bounds__(256, 2) void attn_kernel(
    const float* __restrict__ mask, float* __restrict__ out)
{
    extern __shared__ __align__(16) char smraw[];
    __nv_bfloat16* sQh = (__nv_bfloat16*)(smraw);                 // [128][72]
    __nv_bfloat16* sQl = (__nv_bfloat16*)(smraw + 18432);
    __nv_bfloat16* sKh = (__nv_bfloat16*)(smraw + 36864);         // [64][72]
    __nv_bfloat16* sKl = (__nv_bfloat16*)(smraw + 46080);
    __nv_bfloat16* sVh = (__nv_bfloat16*)(smraw + 55296);         // V^T [d=64][kc=72]
    __nv_bfloat16* sVl = (__nv_bfloat16*)(smraw + 64512);

    const int tid  = threadIdx.x;
    const int warp = tid >> 5;
    const int l    = tid & 31;
    const int rt   = blockIdx.x;          // q tile of 128
    const int bh   = blockIdx.y;
    const int bi   = bh >> 4;
    const int h    = bh & 15;

    const size_t bhoff = (size_t)bh * L_SEQ;

    // load Q tile (pre-scaled hi/lo bf16): 128 rows x 8 granules x 2 arrays
    #pragma unroll
    for (int i = 0; i < 4; i++) {
        int g = tid + i * 256;
        int row = g >> 3, c8 = g & 7;
        *(uint4*)&sQh[row * 72 + c8 * 8] =
            *(const uint4*)&g_qh[(bhoff + rt * 128 + row) * HDIM + c8 * 8];
        *(uint4*)&sQl[row * 72 + c8 * 8] =
            *(const uint4*)&g_ql[(bhoff + rt * 128 + row) * HDIM + c8 * 8];
    }

    const int qr   = warp * 16 + (l >> 2);   // local q row for c0,c1
    const int tcol = (l & 3) * 2;

    float mi0 = -1e30f, mi1 = -1e30f, li0 = 0.0f, li1 = 0.0f;
    float oacc[8][4] = {};

    const float* Mbase = mask + ((size_t)bi * L_SEQ + rt * 128) * L_SEQ;

    for (int kt = 0; kt < L_SEQ / 64; kt++) {
        if (kt) __syncthreads();
        // K tile hi/lo: 64 rows x 8 granules x 2 arrays = 1024 / 256 thr
        #pragma unroll
        for (int i = 0; i < 2; i++) {
            int g = tid + i * 256;
            int row = g >> 3, c8 = g & 7;
            *(uint4*)&sKh[row * 72 + c8 * 8] =
                *(const uint4*)&g_kh[(bhoff + kt * 64 + row) * HDIM + c8 * 8];
            *(uint4*)&sKl[row * 72 + c8 * 8] =
                *(const uint4*)&g_kl[(bhoff + kt * 64 + row) * HDIM + c8 * 8];
        }
        // V tile: transpose + split. 2048 u32 targets, diagonal mapping for
        // conflict-free STS (bank = 4b + a + const, bijective over the warp).
        #pragma unroll
        for (int i = 0; i < 8; i++) {
            int f = tid + i * 256;
            int d = f & 63;
            int aa = f >> 6;
            int kc2 = (aa + (d >> 3)) & 31;
            const float* vp = &g_vv[(bhoff + kt * 64 + kc2 * 2) * HDIM + d];
            float v0 = vp[0], v1 = vp[HDIM];
            __nv_bfloat16 h0 = __float2bfloat16(v0);
            __nv_bfloat16 h1 = __float2bfloat16(v1);
            __nv_bfloat162 hp; hp.x = h0; hp.y = h1;
            *(unsigned*)&sVh[d * 72 + kc2 * 2] = *(unsigned*)&hp;
            *(unsigned*)&sVl[d * 72 + kc2 * 2] =
                pack_bf16(v0 - __bfloat162float(h0), v1 - __bfloat162float(h1));
        }
        __syncthreads();

        // ---- S = Q K^T (pre-scaled) ----
        float sacc[8][4] = {};
        #pragma unroll
        for (int ks = 0; ks < 4; ks++) {
            const int ac = ks * 16 + tcol;
            unsigned ah[4], al[4];
            ah[0] = *(unsigned*)&sQh[qr * 72 + ac];
            ah[1] = *(unsigned*)&sQh[(qr + 8) * 72 + ac];
            ah[2] = *(unsigned*)&sQh[qr * 72 + ac + 8];
            ah[3] = *(unsigned*)&sQh[(qr + 8) * 72 + ac + 8];
            al[0] = *(unsigned*)&sQl[qr * 72 + ac];
            al[1] = *(unsigned*)&sQl[(qr + 8) * 72 + ac];
            al[2] = *(unsigned*)&sQl[qr * 72 + ac + 8];
            al[3] = *(unsigned*)&sQl[(qr + 8) * 72 + ac + 8];
            #pragma unroll
            for (int nt = 0; nt < 8; nt++) {
                const int br = nt * 8 + (l >> 2);
                unsigned b0h = *(unsigned*)&sKh[br * 72 + ac];
                unsigned b1h = *(unsigned*)&sKh[br * 72 + ac + 8];
                unsigned b0l = *(unsigned*)&sKl[br * 72 + ac];
                unsigned b1l = *(unsigned*)&sKl[br * 72 + ac + 8];
                mma16816(sacc[nt], ah, b0h, b1h);
                mma16816(sacc[nt], ah, b0l, b1l);
                mma16816(sacc[nt], al, b0h, b1h);
            }
        }

        // ---- mask add ----
        const float* M0 = Mbase + (size_t)qr * L_SEQ + kt * 64;
        const float* M1 = M0 + 8 * L_SEQ;
        #pragma unroll
        for (int nt = 0; nt < 8; nt++) {
            float2 mk0 = *(const float2*)&M0[nt * 8 + tcol];
            float2 mk1 = *(const float2*)&M1[nt * 8 + tcol];
            sacc[nt][0] += mk0.x; sacc[nt][1] += mk0.y;
            sacc[nt][2] += mk1.x; sacc[nt][3] += mk1.y;
        }

        // ---- online softmax (reduce over 4 lanes of the quad) ----
        float mx0 = -1e30f, mx1 = -1e30f;
        #pragma unroll
        for (int nt = 0; nt < 8; nt++) {
            mx0 = fmaxf(mx0, fmaxf(sacc[nt][0], sacc[nt][1]));
            mx1 = fmaxf(mx1, fmaxf(sacc[nt][2], sacc[nt][3]));
        }
        mx0 = fmaxf(mx0, __shfl_xor_sync(0xffffffffu, mx0, 1));
        mx0 = fmaxf(mx0, __shfl_xor_sync(0xffffffffu, mx0, 2));
        mx1 = fmaxf(mx1, __shfl_xor_sync(0xffffffffu, mx1, 1));
        mx1 = fmaxf(mx1, __shfl_xor_sync(0xffffffffu, mx1, 2));
        float mn0 = fmaxf(mi0, mx0), mn1 = fmaxf(mi1, mx1);
        float al0 = __expf(mi0 - mn0), al1 = __expf(mi1 - mn1);
        mi0 = mn0; mi1 = mn1;
        float sum0 = 0.0f, sum1 = 0.0f;
        #pragma unroll
        for (int nt = 0; nt < 8; nt++) {
            sacc[nt][0] = __expf(sacc[nt][0] - mn0);
            sacc[nt][1] = __expf(sacc[nt][1] - mn0);
            sacc[nt][2] = __expf(sacc[nt][2] - mn1);
            sacc[nt][3] = __expf(sacc[nt][3] - mn1);
            sum0 += sacc[nt][0] + sacc[nt][1];
            sum1 += sacc[nt][2] + sacc[nt][3];
        }
        sum0 += __shfl_xor_sync(0xffffffffu, sum0, 1);
        sum0 += __shfl_xor_sync(0xffffffffu, sum0, 2);
        sum1 += __shfl_xor_sync(0xffffffffu, sum1, 1);
        sum1 += __shfl_xor_sync(0xffffffffu, sum1, 2);
        li0 = li0 * al0 + sum0;
        li1 = li1 * al1 + sum1;
        #pragma unroll
        for (int nt = 0; nt < 8; nt++) {
            oacc[nt][0] *= al0; oacc[nt][1] *= al0;
            oacc[nt][2] *= al1; oacc[nt][3] *= al1;
        }

        // ---- O += P V : S-fragments ARE the A-fragments (layout identity) ----
        #pragma unroll
        for (int kk = 0; kk < 4; kk++) {
            unsigned pah[4], pal[4];
            split2(sacc[2 * kk][0],     sacc[2 * kk][1],     pah[0], pal[0]);
            split2(sacc[2 * kk][2],     sacc[2 * kk][3],     pah[1], pal[1]);
            split2(sacc[2 * kk + 1][0], sacc[2 * kk + 1][1], pah[2], pal[2]);
            split2(sacc[2 * kk + 1][2], sacc[2 * kk + 1][3], pah[3], pal[3]);
            const int bc = kk * 16 + tcol;
            #pragma unroll
            for (int nt = 0; nt < 8; nt++) {
                const int vr = nt * 8 + (l >> 2);    // n = d index
                unsigned b0h = *(unsigned*)&sVh[vr * 72 + bc];
                unsigned b1h = *(unsigned*)&sVh[vr * 72 + bc + 8];
                unsigned b0l = *(unsigned*)&sVl[vr * 72 + bc];
                unsigned b1l = *(unsigned*)&sVl[vr * 72 + bc + 8];
                mma16816(oacc[nt], pah, b0h, b1h);
                mma16816(oacc[nt], pah, b0l, b1l);
                mma16816(oacc[nt], pal, b0h, b1h);
            }
        }
    }

    // ---- normalize + write out[b, l, h*64 + d] ----
    const float inv0 = 1.0f / li0, inv1 = 1.0f / li1;
    const int gr0 = rt * 128 + qr;
    #pragma unroll
    for (int nt = 0; nt < 8; nt++) {
        const int d = nt * 8 + tcol;
        *(float2*)&out[((size_t)bi * L_SEQ + gr0) * DMODEL + h * HDIM + d] =
            make_float2(oacc[nt][0] * inv0, oacc[nt][1] * inv0);
        *(float2*)&out[((size_t)bi * L_SEQ + gr0 + 8) * DMODEL + h * HDIM + d] =
            make_float2(oacc[nt][2] * inv1, oacc[nt][3] * inv1);
    }
}

// ---------------------------------------------------------------------------
extern "C" void kernel_launch(void* const* d_in, const int* in_sizes, int n_in,
                              void* d_out, int out_size)
{
    const float* x    = (const float*)d_in[0];
    const float* mask = (const float*)d_in[1];
    const float* wq   = (const float*)d_in[2];
    const float* bq   = (const float*)d_in[3];
    const float* wk   = (const float*)d_in[4];
    const float* bk   = (const float*)d_in[5];
    const float* wv   = (const float*)d_in[6];
    const float* bv   = (const float*)d_in[7];
    float* out = (float*)d_out;

    split_all<<<11264, 256>>>(x, wq, wk, wv);

    dim3 gq(128, 16, 3);
    qkv_kernel<<<gq, 128>>>(bq, bk, bv);

    const int smem_attn = 73728;
    cudaFuncSetAttribute(attn_kernel,
                         cudaFuncAttributeMaxDynamicSharedMemorySize, smem_attn);
    dim3 ga(16, 64);
    attn_kernel<<<ga, 256, smem_attn>>>(mask, out);
}

// round 7
// speedup vs baseline: 3.0577x; 1.0873x over previous
#include <cuda_runtime.h>
#include <cuda_bf16.h>

#define L_SEQ  2048
#define NB     4
#define NHEAD  16
#define HDIM   64
#define DMODEL 1024

// ---------------------------------------------------------------------------
// Device-global scratch: Q/K tf32-rounded fp32 (Q pre-scaled by 0.125), V fp32
// Layout [bh][l][64]
// ---------------------------------------------------------------------------
__device__ float g_q[(size_t)NB * NHEAD * L_SEQ * HDIM];
__device__ float g_k[(size_t)NB * NHEAD * L_SEQ * HDIM];
__device__ float g_vv[(size_t)NB * NHEAD * L_SEQ * HDIM];

// ---------------------------------------------------------------------------
// Helpers
// ---------------------------------------------------------------------------
__device__ __forceinline__ unsigned cvt_tf32(float f) {
    unsigned u;
    asm("cvt.rna.tf32.f32 %0, %1;" : "=r"(u) : "f"(f));
    return u;
}
__device__ __forceinline__ unsigned pack_bf16(float a, float b) {
    __nv_bfloat162 t = __floats2bfloat162_rn(a, b);
    return *(unsigned*)&t;
}
// split (a,b) into hi/lo bf16 pairs packed as u32
__device__ __forceinline__ void split2(float a, float b, unsigned &hi, unsigned &lo) {
    __nv_bfloat16 ah = __float2bfloat16(a);
    __nv_bfloat16 bh = __float2bfloat16(b);
    __nv_bfloat162 hv; hv.x = ah; hv.y = bh;
    hi = *(unsigned*)&hv;
    lo = pack_bf16(a - __bfloat162float(ah), b - __bfloat162float(bh));
}
// bf16 m16n8k16
__device__ __forceinline__ void mma16816(float c[4], const unsigned a[4],
                                         unsigned b0, unsigned b1) {
    asm volatile(
        "mma.sync.aligned.m16n8k16.row.col.f32.bf16.bf16.f32 "
        "{%0,%1,%2,%3}, {%4,%5,%6,%7}, {%8,%9}, {%0,%1,%2,%3};"
        : "+f"(c[0]), "+f"(c[1]), "+f"(c[2]), "+f"(c[3])
        : "r"(a[0]), "r"(a[1]), "r"(a[2]), "r"(a[3]), "r"(b0), "r"(b1));
}
// tf32 m16n8k8
__device__ __forceinline__ void mma1688(float c[4], const unsigned a[4],
                                        unsigned b0, unsigned b1) {
    asm volatile(
        "mma.sync.aligned.m16n8k8.row.col.f32.tf32.tf32.f32 "
        "{%0,%1,%2,%3}, {%4,%5,%6,%7}, {%8,%9}, {%0,%1,%2,%3};"
        : "+f"(c[0]), "+f"(c[1]), "+f"(c[2]), "+f"(c[3])
        : "r"(a[0]), "r"(a[1]), "r"(a[2]), "r"(a[3]), "r"(b0), "r"(b1));
}

// ---------------------------------------------------------------------------
// QKV GEMM via tf32 mma.sync: out[m,n] = sum_k x[m,k] w[n,k] + b[n]
// CTA: 128 thr (4 warps), tile 64m x 64n, k-chunks of 64. grid (128,16,3).
// Q (z=0): scaled by 0.125, tf32-rounded -> g_q. K (z=1): tf32 -> g_k.
// V (z=2): fp32 -> g_vv.
// ---------------------------------------------------------------------------
__global__ __launch_bounds__(128) void qkv_kernel(
    const float* __restrict__ x,
    const float* __restrict__ wq, const float* __restrict__ bq,
    const float* __restrict__ wk, const float* __restrict__ bk,
    const float* __restrict__ wv, const float* __restrict__ bv)
{
    __shared__ __align__(16) float sx[64 * 68];
    __shared__ __align__(16) float sw[64 * 68];

    const int z    = blockIdx.z;
    const int tid  = threadIdx.x;
    const int warp = tid >> 5;
    const int l    = tid & 31;
    const int m0   = blockIdx.x * 64;
    const int h    = blockIdx.y;
    const int n0   = h * 64;

    const float* w;
    const float* bias;
    if (z == 0)      { w = wq; bias = bq; }
    else if (z == 1) { w = wk; bias = bk; }
    else             { w = wv; bias = bv; }

    float acc[8][4] = {};
    const unsigned* sxu = (const unsigned*)sx;
    const unsigned* swu = (const unsigned*)sw;

    for (int k0 = 0; k0 < DMODEL; k0 += 64) {
        if (k0) __syncthreads();
        // 64 rows x 16 float4 = 1024 granules per array / 128 thr = 8 iters
        #pragma unroll
        for (int i = 0; i < 8; i++) {
            int g = tid + i * 128;
            int row = g >> 4, c4 = g & 15;
            float4 vx = *(const float4*)&x[(size_t)(m0 + row) * DMODEL + k0 + c4 * 4];
            float4 vw = *(const float4*)&w[(size_t)(n0 + row) * DMODEL + k0 + c4 * 4];
            unsigned* dx = (unsigned*)&sx[row * 68 + c4 * 4];
            unsigned* dw = (unsigned*)&sw[row * 68 + c4 * 4];
            dx[0] = cvt_tf32(vx.x); dx[1] = cvt_tf32(vx.y);
            dx[2] = cvt_tf32(vx.z); dx[3] = cvt_tf32(vx.w);
            dw[0] = cvt_tf32(vw.x); dw[1] = cvt_tf32(vw.y);
            dw[2] = cvt_tf32(vw.z); dw[3] = cvt_tf32(vw.w);
        }
        __syncthreads();

        const int ar = warp * 16 + (l >> 2);
        const int tc = l & 3;
        #pragma unroll
        for (int ks = 0; ks < 8; ks++) {
            const int ac = ks * 8 + tc;
            unsigned a[4];
            a[0] = sxu[ar * 68 + ac];
            a[1] = sxu[(ar + 8) * 68 + ac];
            a[2] = sxu[ar * 68 + ac + 4];
            a[3] = sxu[(ar + 8) * 68 + ac + 4];
            #pragma unroll
            for (int nt = 0; nt < 8; nt++) {
                const int br = nt * 8 + (l >> 2);
                unsigned b0 = swu[br * 68 + ac];
                unsigned b1 = swu[br * 68 + ac + 4];
                mma1688(acc[nt], a, b0, b1);
            }
        }
    }

    // epilogue
    const int r0 = m0 + warp * 16 + (l >> 2);
    const int c0 = (l & 3) * 2;
    const int bi = m0 >> 11;
    const int lg = r0 & (L_SEQ - 1);
    const size_t bhbase = (size_t)(bi * NHEAD + h) * L_SEQ;

    #pragma unroll
    for (int nt = 0; nt < 8; nt++) {
        const int d = nt * 8 + c0;
        float2 b2 = *(const float2*)&bias[n0 + d];
        float v0 = acc[nt][0] + b2.x, v1 = acc[nt][1] + b2.y;   // row lg
        float v2 = acc[nt][2] + b2.x, v3 = acc[nt][3] + b2.y;   // row lg+8
        if (z == 2) {
            *(float2*)&g_vv[(bhbase + lg)     * HDIM + d] = make_float2(v0, v1);
            *(float2*)&g_vv[(bhbase + lg + 8) * HDIM + d] = make_float2(v2, v3);
        } else {
            if (z == 0) { v0 *= 0.125f; v1 *= 0.125f; v2 *= 0.125f; v3 *= 0.125f; }
            float* dst = (z == 0) ? g_q : g_k;
            *(float2*)&dst[(bhbase + lg) * HDIM + d] =
                make_float2(__uint_as_float(cvt_tf32(v0)), __uint_as_float(cvt_tf32(v1)));
            *(float2*)&dst[(bhbase + lg + 8) * HDIM + d] =
                make_float2(__uint_as_float(cvt_tf32(v2)), __uint_as_float(cvt_tf32(v3)));
        }
    }
}

// ---------------------------------------------------------------------------
// Flash attention. QK^T via tf32 mma, PV via bf16 3-pass split (layout
// identity S-frag -> A-frag). CTA: 256 thr (8 warps), 128 q-rows, K-tiles
// of 64. grid (16, 64).
// ---------------------------------------------------------------------------
__global__ __launch_bounds__(256, 2) void attn_kernel(
    const float* __restrict__ mask, float* __restrict__ out)
{
    extern __shared__ __align__(16) char smraw[];
    float* sQ = (float*)(smraw);                           // [128][68] f32 tf32
    float* sK = (float*)(smraw + 34816);                   // [64][68]  f32 tf32
    __nv_bfloat16* sVh = (__nv_bfloat16*)(smraw + 52224);  // V^T [d=64][kc=72]
    __nv_bfloat16* sVl = (__nv_bfloat16*)(smraw + 61440);

    const int tid  = threadIdx.x;
    const int warp = tid >> 5;
    const int l    = tid & 31;
    const int rt   = blockIdx.x;          // q tile of 128
    const int bh   = blockIdx.y;
    const int bi   = bh >> 4;
    const int h    = bh & 15;

    const size_t bhoff = (size_t)bh * L_SEQ;
    const unsigned* sQu = (const unsigned*)sQ;
    const unsigned* sKu = (const unsigned*)sK;

    // load Q tile: 8192 floats = 2048 float4 / 256 thr = 8 iters
    #pragma unroll
    for (int i = 0; i < 8; i++) {
        int g = tid + i * 256;
        int row = g >> 4, c4 = g & 15;
        *(float4*)&sQ[row * 68 + c4 * 4] =
            *(const float4*)&g_q[(bhoff + rt * 128 + row) * HDIM + c4 * 4];
    }

    const int qr   = warp * 16 + (l >> 2);
    const int tc   = l & 3;
    const int tcol = tc * 2;

    float mi0 = -1e30f, mi1 = -1e30f, li0 = 0.0f, li1 = 0.0f;
    float oacc[8][4] = {};

    const float* Mbase = mask + ((size_t)bi * L_SEQ + rt * 128) * L_SEQ;

    for (int kt = 0; kt < L_SEQ / 64; kt++) {
        if (kt) __syncthreads();
        // K tile: 4096 floats = 1024 float4 / 256 thr = 4 iters
        #pragma unroll
        for (int i = 0; i < 4; i++) {
            int g = tid + i * 256;
            int row = g >> 4, c4 = g & 15;
            *(float4*)&sK[row * 68 + c4 * 4] =
                *(const float4*)&g_k[(bhoff + kt * 64 + row) * HDIM + c4 * 4];
        }
        // V tile: transpose + split to bf16 hi/lo. Diagonal mapping keeps STS
        // conflict-free (bank = 4b + a + const, bijective over the warp).
        #pragma unroll
        for (int i = 0; i < 8; i++) {
            int f = tid + i * 256;
            int d = f & 63;
            int aa = f >> 6;
            int kc2 = (aa + (d >> 3)) & 31;
            const float* vp = &g_vv[(bhoff + kt * 64 + kc2 * 2) * HDIM + d];
            float v0 = vp[0], v1 = vp[HDIM];
            __nv_bfloat16 h0 = __float2bfloat16(v0);
            __nv_bfloat16 h1 = __float2bfloat16(v1);
            __nv_bfloat162 hp; hp.x = h0; hp.y = h1;
            *(unsigned*)&sVh[d * 72 + kc2 * 2] = *(unsigned*)&hp;
            *(unsigned*)&sVl[d * 72 + kc2 * 2] =
                pack_bf16(v0 - __bfloat162float(h0), v1 - __bfloat162float(h1));
        }
        __syncthreads();

        // ---- S = Q K^T  (tf32, single pass, Q pre-scaled) ----
        float sacc[8][4] = {};
        #pragma unroll
        for (int ks = 0; ks < 8; ks++) {
            const int ac = ks * 8 + tc;
            unsigned a[4];
            a[0] = sQu[qr * 68 + ac];
            a[1] = sQu[(qr + 8) * 68 + ac];
            a[2] = sQu[qr * 68 + ac + 4];
            a[3] = sQu[(qr + 8) * 68 + ac + 4];
            #pragma unroll
            for (int nt = 0; nt < 8; nt++) {
                const int br = nt * 8 + (l >> 2);
                unsigned b0 = sKu[br * 68 + ac];
                unsigned b1 = sKu[br * 68 + ac + 4];
                mma1688(sacc[nt], a, b0, b1);
            }
        }

        // ---- mask add ----
        const float* M0 = Mbase + (size_t)qr * L_SEQ + kt * 64;
        const float* M1 = M0 + 8 * L_SEQ;
        #pragma unroll
        for (int nt = 0; nt < 8; nt++) {
            float2 mk0 = *(const float2*)&M0[nt * 8 + tcol];
            float2 mk1 = *(const float2*)&M1[nt * 8 + tcol];
            sacc[nt][0] += mk0.x; sacc[nt][1] += mk0.y;
            sacc[nt][2] += mk1.x; sacc[nt][3] += mk1.y;
        }

        // ---- online softmax (reduce over 4 lanes of the quad) ----
        float mx0 = -1e30f, mx1 = -1e30f;
        #pragma unroll
        for (int nt = 0; nt < 8; nt++) {
            mx0 = fmaxf(mx0, fmaxf(sacc[nt][0], sacc[nt][1]));
            mx1 = fmaxf(mx1, fmaxf(sacc[nt][2], sacc[nt][3]));
        }
        mx0 = fmaxf(mx0, __shfl_xor_sync(0xffffffffu, mx0, 1));
        mx0 = fmaxf(mx0, __shfl_xor_sync(0xffffffffu, mx0, 2));
        mx1 = fmaxf(mx1, __shfl_xor_sync(0xffffffffu, mx1, 1));
        mx1 = fmaxf(mx1, __shfl_xor_sync(0xffffffffu, mx1, 2));
        float mn0 = fmaxf(mi0, mx0), mn1 = fmaxf(mi1, mx1);
        float al0 = __expf(mi0 - mn0), al1 = __expf(mi1 - mn1);
        mi0 = mn0; mi1 = mn1;
        float sum0 = 0.0f, sum1 = 0.0f;
        #pragma unroll
        for (int nt = 0; nt < 8; nt++) {
            sacc[nt][0] = __expf(sacc[nt][0] - mn0);
            sacc[nt][1] = __expf(sacc[nt][1] - mn0);
            sacc[nt][2] = __expf(sacc[nt][2] - mn1);
            sacc[nt][3] = __expf(sacc[nt][3] - mn1);
            sum0 += sacc[nt][0] + sacc[nt][1];
            sum1 += sacc[nt][2] + sacc[nt][3];
        }
        sum0 += __shfl_xor_sync(0xffffffffu, sum0, 1);
        sum0 += __shfl_xor_sync(0xffffffffu, sum0, 2);
        sum1 += __shfl_xor_sync(0xffffffffu, sum1, 1);
        sum1 += __shfl_xor_sync(0xffffffffu, sum1, 2);
        li0 = li0 * al0 + sum0;
        li1 = li1 * al1 + sum1;
        #pragma unroll
        for (int nt = 0; nt < 8; nt++) {
            oacc[nt][0] *= al0; oacc[nt][1] *= al0;
            oacc[nt][2] *= al1; oacc[nt][3] *= al1;
        }

        // ---- O += P V (bf16 3-pass; S-fragments ARE the A-fragments) ----
        #pragma unroll
        for (int kk = 0; kk < 4; kk++) {
            unsigned pah[4], pal[4];
            split2(sacc[2 * kk][0],     sacc[2 * kk][1],     pah[0], pal[0]);
            split2(sacc[2 * kk][2],     sacc[2 * kk][3],     pah[1], pal[1]);
            split2(sacc[2 * kk + 1][0], sacc[2 * kk + 1][1], pah[2], pal[2]);
            split2(sacc[2 * kk + 1][2], sacc[2 * kk + 1][3], pah[3], pal[3]);
            const int bc = kk * 16 + tcol;
            #pragma unroll
            for (int nt = 0; nt < 8; nt++) {
                const int vr = nt * 8 + (l >> 2);    // n = d index
                unsigned b0h = *(unsigned*)&sVh[vr * 72 + bc];
                unsigned b1h = *(unsigned*)&sVh[vr * 72 + bc + 8];
                unsigned b0l = *(unsigned*)&sVl[vr * 72 + bc];
                unsigned b1l = *(unsigned*)&sVl[vr * 72 + bc + 8];
                mma16816(oacc[nt], pah, b0h, b1h);
                mma16816(oacc[nt], pah, b0l, b1l);
                mma16816(oacc[nt], pal, b0h, b1h);
            }
        }
    }

    // ---- normalize + write out[b, l, h*64 + d] ----
    const float inv0 = 1.0f / li0, inv1 = 1.0f / li1;
    const int gr0 = rt * 128 + qr;
    #pragma unroll
    for (int nt = 0; nt < 8; nt++) {
        const int d = nt * 8 + tcol;
        *(float2*)&out[((size_t)bi * L_SEQ + gr0) * DMODEL + h * HDIM + d] =
            make_float2(oacc[nt][0] * inv0, oacc[nt][1] * inv0);
        *(float2*)&out[((size_t)bi * L_SEQ + gr0 + 8) * DMODEL + h * HDIM + d] =
            make_float2(oacc[nt][2] * inv1, oacc[nt][3] * inv1);
    }
}

// ---------------------------------------------------------------------------
extern "C" void kernel_launch(void* const* d_in, const int* in_sizes, int n_in,
                              void* d_out, int out_size)
{
    const float* x    = (const float*)d_in[0];
    const float* mask = (const float*)d_in[1];
    const float* wq   = (const float*)d_in[2];
    const float* bq   = (const float*)d_in[3];
    const float* wk   = (const float*)d_in[4];
    const float* bk   = (const float*)d_in[5];
    const float* wv   = (const float*)d_in[6];
    const float* bv   = (const float*)d_in[7];
    float* out = (float*)d_out;

    dim3 gq(128, 16, 3);
    qkv_kernel<<<gq, 128>>>(x, wq, bq, wk, bk, wv, bv);

    const int smem_attn = 70656;
    cudaFuncSetAttribute(attn_kernel,
                         cudaFuncAttributeMaxDynamicSharedMemorySize, smem_attn);
    dim3 ga(16, 64);
    attn_kernel<<<ga, 256, smem_attn>>>(mask, out);
}

// round 11
// speedup vs baseline: 3.3646x; 1.1004x over previous
#include <cuda_runtime.h>
#include <cuda_bf16.h>

#define L_SEQ  2048
#define NB     4
#define NHEAD  16
#define HDIM   64
#define DMODEL 1024

// ---------------------------------------------------------------------------
// Device-global scratch (tf32-rounded fp32; Q pre-scaled by 0.125)
// g_q/g_k: [bh][l][64].  g_vt: V transposed [bh][d][L]
// ---------------------------------------------------------------------------
__device__ float g_q[(size_t)NB * NHEAD * L_SEQ * HDIM];
__device__ float g_k[(size_t)NB * NHEAD * L_SEQ * HDIM];
__device__ float g_vt[(size_t)NB * NHEAD * HDIM * L_SEQ];

// ---------------------------------------------------------------------------
// Helpers
// ---------------------------------------------------------------------------
__device__ __forceinline__ unsigned cvt_tf32(float f) {
    unsigned u;
    asm("cvt.rna.tf32.f32 %0, %1;" : "=r"(u) : "f"(f));
    return u;
}
// tf32 m16n8k8
__device__ __forceinline__ void mma1688(float c[4], const unsigned a[4],
                                        unsigned b0, unsigned b1) {
    asm volatile(
        "mma.sync.aligned.m16n8k8.row.col.f32.tf32.tf32.f32 "
        "{%0,%1,%2,%3}, {%4,%5,%6,%7}, {%8,%9}, {%0,%1,%2,%3};"
        : "+f"(c[0]), "+f"(c[1]), "+f"(c[2]), "+f"(c[3])
        : "r"(a[0]), "r"(a[1]), "r"(a[2]), "r"(a[3]), "r"(b0), "r"(b1));
}

// ---------------------------------------------------------------------------
// QKV GEMM via tf32 mma.sync: out[m,n] = sum_k x[m,k] w[n,k] + b[n]
// CTA: 128 thr (4 warps), tile 64m x 64n, k-chunks of 64. grid (128,16,3).
// Q (z=0): scaled by 0.125, tf32 -> g_q. K (z=1): tf32 -> g_k.
// V (z=2): tf32, TRANSPOSED via smem staging -> g_vt[bh][d][L] (coalesced).
// ---------------------------------------------------------------------------
__global__ __launch_bounds__(128) void qkv_kernel(
    const float* __restrict__ x,
    const float* __restrict__ wq, const float* __restrict__ bq,
    const float* __restrict__ wk, const float* __restrict__ bk,
    const float* __restrict__ wv, const float* __restrict__ bv)
{
    __shared__ __align__(16) float sx[64 * 68];
    __shared__ __align__(16) float sw[64 * 68];

    const int z    = blockIdx.z;
    const int tid  = threadIdx.x;
    const int warp = tid >> 5;
    const int l    = tid & 31;
    const int m0   = blockIdx.x * 64;
    const int h    = blockIdx.y;
    const int n0   = h * 64;

    const float* w;
    const float* bias;
    if (z == 0)      { w = wq; bias = bq; }
    else if (z == 1) { w = wk; bias = bk; }
    else             { w = wv; bias = bv; }

    float acc[8][4] = {};
    const unsigned* sxu = (const unsigned*)sx;
    const unsigned* swu = (const unsigned*)sw;

    for (int k0 = 0; k0 < DMODEL; k0 += 64) {
        if (k0) __syncthreads();
        #pragma unroll
        for (int i = 0; i < 8; i++) {
            int g = tid + i * 128;
            int row = g >> 4, c4 = g & 15;
            float4 vx = *(const float4*)&x[(size_t)(m0 + row) * DMODEL + k0 + c4 * 4];
            float4 vw = *(const float4*)&w[(size_t)(n0 + row) * DMODEL + k0 + c4 * 4];
            unsigned* dx = (unsigned*)&sx[row * 68 + c4 * 4];
            unsigned* dw = (unsigned*)&sw[row * 68 + c4 * 4];
            dx[0] = cvt_tf32(vx.x); dx[1] = cvt_tf32(vx.y);
            dx[2] = cvt_tf32(vx.z); dx[3] = cvt_tf32(vx.w);
            dw[0] = cvt_tf32(vw.x); dw[1] = cvt_tf32(vw.y);
            dw[2] = cvt_tf32(vw.z); dw[3] = cvt_tf32(vw.w);
        }
        __syncthreads();

        const int ar = warp * 16 + (l >> 2);
        const int tc = l & 3;
        #pragma unroll
        for (int ks = 0; ks < 8; ks++) {
            const int ac = ks * 8 + tc;
            unsigned a[4];
            a[0] = sxu[ar * 68 + ac];
            a[1] = sxu[(ar + 8) * 68 + ac];
            a[2] = sxu[ar * 68 + ac + 4];
            a[3] = sxu[(ar + 8) * 68 + ac + 4];
            #pragma unroll
            for (int nt = 0; nt < 8; nt++) {
                const int br = nt * 8 + (l >> 2);
                unsigned b0 = swu[br * 68 + ac];
                unsigned b1 = swu[br * 68 + ac + 4];
                mma1688(acc[nt], a, b0, b1);
            }
        }
    }

    // epilogue
    const int lm = warp * 16 + (l >> 2);        // local m (0..63), rows lm, lm+8
    const int c0 = (l & 3) * 2;
    const int bi = m0 >> 11;
    const int lg = (m0 + lm) & (L_SEQ - 1);     // l within batch
    const size_t bhbase = (size_t)(bi * NHEAD + h) * L_SEQ;

    if (z == 2) {
        // stage transposed into sx as [d][m] (stride 68), then coalesced out.
        __syncthreads();   // uniform: all CTA threads have same z
        #pragma unroll
        for (int nt = 0; nt < 8; nt++) {
            const int d = nt * 8 + c0;
            float2 b2 = *(const float2*)&bias[n0 + d];
            // bank of sx[d*68+lm]: (32nt + 8tc + rq) mod 32 — bijective/warp
            sx[d * 68 + lm]           = __uint_as_float(cvt_tf32(acc[nt][0] + b2.x));
            sx[(d + 1) * 68 + lm]     = __uint_as_float(cvt_tf32(acc[nt][1] + b2.y));
            sx[d * 68 + lm + 8]       = __uint_as_float(cvt_tf32(acc[nt][2] + b2.x));
            sx[(d + 1) * 68 + lm + 8] = __uint_as_float(cvt_tf32(acc[nt][3] + b2.y));
        }
        __syncthreads();
        // 64 d-rows x 64 m-cols = 1024 float4 / 128 thr = 8 iters, coalesced
        const size_t vbase = (size_t)(bi * NHEAD + h) * HDIM * L_SEQ;
        const int l0 = m0 & (L_SEQ - 1);
        #pragma unroll
        for (int i = 0; i < 8; i++) {
            int g = tid + i * 128;
            int row = g >> 4, c4 = g & 15;
            *(float4*)&g_vt[vbase + (size_t)row * L_SEQ + l0 + c4 * 4] =
                *(const float4*)&sx[row * 68 + c4 * 4];
        }
    } else {
        float* dst = (z == 0) ? g_q : g_k;
        const float sc = (z == 0) ? 0.125f : 1.0f;
        #pragma unroll
        for (int nt = 0; nt < 8; nt++) {
            const int d = nt * 8 + c0;
            float2 b2 = *(const float2*)&bias[n0 + d];
            float v0 = (acc[nt][0] + b2.x) * sc, v1 = (acc[nt][1] + b2.y) * sc;
            float v2 = (acc[nt][2] + b2.x) * sc, v3 = (acc[nt][3] + b2.y) * sc;
            *(float2*)&dst[(bhbase + lg) * HDIM + d] =
                make_float2(__uint_as_float(cvt_tf32(v0)), __uint_as_float(cvt_tf32(v1)));
            *(float2*)&dst[(bhbase + lg + 8) * HDIM + d] =
                make_float2(__uint_as_float(cvt_tf32(v2)), __uint_as_float(cvt_tf32(v3)));
        }
    }
}

// ---------------------------------------------------------------------------
// Flash attention, all-tf32 mma. QK^T single pass; PV single pass using the
// S-fragment -> A-fragment slot identity (a = {s0, s2, s1, s3}), B = float2
// from V^T smem. CTA: 256 thr (8 warps), 128 q-rows, K-tiles of 64. grid (16,64).
// ---------------------------------------------------------------------------
__global__ __launch_bounds__(256, 2) void attn_kernel(
    const float* __restrict__ mask, float* __restrict__ out)
{
    extern __shared__ __align__(16) float smem[];
    float* sQ = smem;                 // [128][72] tf32
    float* sK = smem + 128 * 72;      // [64][72]  tf32
    float* sV = smem + 192 * 72;      // [64][72]  V^T: [d][kc], tf32

    const int tid  = threadIdx.x;
    const int warp = tid >> 5;
    const int l    = tid & 31;
    const int rq   = l >> 2;
    const int tcol = (l & 3) * 2;
    const int rt   = blockIdx.x;          // q tile of 128
    const int bh   = blockIdx.y;
    const int bi   = bh >> 4;
    const int h    = bh & 15;

    const size_t bhoff = (size_t)bh * L_SEQ;
    const size_t vtoff = (size_t)bh * HDIM * L_SEQ;

    // load Q tile: 2048 float4 / 256 thr = 8 iters
    #pragma unroll
    for (int i = 0; i < 8; i++) {
        int g = tid + i * 256;
        int row = g >> 4, c4 = g & 15;
        *(float4*)&sQ[row * 72 + c4 * 4] =
            *(const float4*)&g_q[(bhoff + rt * 128 + row) * HDIM + c4 * 4];
    }

    const int qr = warp * 16 + rq;

    float mi0 = -1e30f, mi1 = -1e30f, li0 = 0.0f, li1 = 0.0f;
    float oacc[8][4] = {};

    const float* Mbase = mask + ((size_t)bi * L_SEQ + rt * 128) * L_SEQ;

    for (int kt = 0; kt < L_SEQ / 64; kt++) {
        if (kt) __syncthreads();
        // K tile: 1024 float4 / 256 thr = 4 iters
        #pragma unroll
        for (int i = 0; i < 4; i++) {
            int g = tid + i * 256;
            int row = g >> 4, c4 = g & 15;
            *(float4*)&sK[row * 72 + c4 * 4] =
                *(const float4*)&g_k[(bhoff + kt * 64 + row) * HDIM + c4 * 4];
        }
        // V^T tile: rows d, cols kc — straight coalesced copy, 4 iters
        #pragma unroll
        for (int i = 0; i < 4; i++) {
            int g = tid + i * 256;
            int row = g >> 4, c4 = g & 15;
            *(float4*)&sV[row * 72 + c4 * 4] =
                *(const float4*)&g_vt[vtoff + (size_t)row * L_SEQ + kt * 64 + c4 * 4];
        }
        __syncthreads();

        // ---- S = Q K^T (tf32, Q pre-scaled). Slot pairing: a0/b0 read col
        //      ks*8+2tc, a2/b1 read ks*8+2tc+1 (agreement + coverage). ----
        float sacc[8][4] = {};
        #pragma unroll
        for (int ks = 0; ks < 8; ks++) {
            const int ac = ks * 8 + tcol;
            float2 aq0 = *(const float2*)&sQ[qr * 72 + ac];
            float2 aq1 = *(const float2*)&sQ[(qr + 8) * 72 + ac];
            unsigned a[4] = { __float_as_uint(aq0.x), __float_as_uint(aq1.x),
                              __float_as_uint(aq0.y), __float_as_uint(aq1.y) };
            #pragma unroll
            for (int nt = 0; nt < 8; nt++) {
                float2 b = *(const float2*)&sK[(nt * 8 + rq) * 72 + ac];
                mma1688(sacc[nt], a, __float_as_uint(b.x), __float_as_uint(b.y));
            }
        }

        // ---- mask add (cols nt*8 + 2tc, +1 — natural layout) ----
        const float* M0 = Mbase + (size_t)qr * L_SEQ + kt * 64;
        const float* M1 = M0 + 8 * L_SEQ;
        #pragma unroll
        for (int nt = 0; nt < 8; nt++) {
            float2 mk0 = *(const float2*)&M0[nt * 8 + tcol];
            float2 mk1 = *(const float2*)&M1[nt * 8 + tcol];
            sacc[nt][0] += mk0.x; sacc[nt][1] += mk0.y;
            sacc[nt][2] += mk1.x; sacc[nt][3] += mk1.y;
        }

        // ---- online softmax (reduce over 4 lanes of the quad) ----
        float mx0 = -1e30f, mx1 = -1e30f;
        #pragma unroll
        for (int nt = 0; nt < 8; nt++) {
            mx0 = fmaxf(mx0, fmaxf(sacc[nt][0], sacc[nt][1]));
            mx1 = fmaxf(mx1, fmaxf(sacc[nt][2], sacc[nt][3]));
        }
        mx0 = fmaxf(mx0, __shfl_xor_sync(0xffffffffu, mx0, 1));
        mx0 = fmaxf(mx0, __shfl_xor_sync(0xffffffffu, mx0, 2));
        mx1 = fmaxf(mx1, __shfl_xor_sync(0xffffffffu, mx1, 1));
        mx1 = fmaxf(mx1, __shfl_xor_sync(0xffffffffu, mx1, 2));
        float mn0 = fmaxf(mi0, mx0), mn1 = fmaxf(mi1, mx1);
        float al0 = __expf(mi0 - mn0), al1 = __expf(mi1 - mn1);
        mi0 = mn0; mi1 = mn1;
        float sum0 = 0.0f, sum1 = 0.0f;
        #pragma unroll
        for (int nt = 0; nt < 8; nt++) {
            sacc[nt][0] = __expf(sacc[nt][0] - mn0);
            sacc[nt][1] = __expf(sacc[nt][1] - mn0);
            sacc[nt][2] = __expf(sacc[nt][2] - mn1);
            sacc[nt][3] = __expf(sacc[nt][3] - mn1);
            sum0 += sacc[nt][0] + sacc[nt][1];
            sum1 += sacc[nt][2] + sacc[nt][3];
        }
        sum0 += __shfl_xor_sync(0xffffffffu, sum0, 1);
        sum0 += __shfl_xor_sync(0xffffffffu, sum0, 2);
        sum1 += __shfl_xor_sync(0xffffffffu, sum1, 1);
        sum1 += __shfl_xor_sync(0xffffffffu, sum1, 2);
        li0 = li0 * al0 + sum0;
        li1 = li1 * al1 + sum1;
        #pragma unroll
        for (int nt = 0; nt < 8; nt++) {
            oacc[nt][0] *= al0; oacc[nt][1] *= al0;
            oacc[nt][2] *= al1; oacc[nt][3] *= al1;
        }

        // ---- O += P V (tf32, single pass; S-frag IS the A-frag:
        //      a = {s0, s2, s1, s3}, b = float2 of V^T cols 2tc,2tc+1) ----
        #pragma unroll
        for (int kk = 0; kk < 8; kk++) {
            unsigned a[4] = { cvt_tf32(sacc[kk][0]), cvt_tf32(sacc[kk][2]),
                              cvt_tf32(sacc[kk][1]), cvt_tf32(sacc[kk][3]) };
            const int bc = kk * 8 + tcol;
            #pragma unroll
            for (int nt = 0; nt < 8; nt++) {
                float2 b = *(const float2*)&sV[(nt * 8 + rq) * 72 + bc];
                mma1688(oacc[nt], a, __float_as_uint(b.x), __float_as_uint(b.y));
            }
        }
    }

    // ---- normalize + write out[b, l, h*64 + d] ----
    const float inv0 = 1.0f / li0, inv1 = 1.0f / li1;
    const int gr0 = rt * 128 + qr;
    #pragma unroll
    for (int nt = 0; nt < 8; nt++) {
        const int d = nt * 8 + tcol;
        *(float2*)&out[((size_t)bi * L_SEQ + gr0) * DMODEL + h * HDIM + d] =
            make_float2(oacc[nt][0] * inv0, oacc[nt][1] * inv0);
        *(float2*)&out[((size_t)bi * L_SEQ + gr0 + 8) * DMODEL + h * HDIM + d] =
            make_float2(oacc[nt][2] * inv1, oacc[nt][3] * inv1);
    }
}

// ---------------------------------------------------------------------------
extern "C" void kernel_launch(void* const* d_in, const int* in_sizes, int n_in,
                              void* d_out, int out_size)
{
    const float* x    = (const float*)d_in[0];
    const float* mask = (const float*)d_in[1];
    const float* wq   = (const float*)d_in[2];
    const float* bq   = (const float*)d_in[3];
    const float* wk   = (const float*)d_in[4];
    const float* bk   = (const float*)d_in[5];
    const float* wv   = (const float*)d_in[6];
    const float* bv   = (const float*)d_in[7];
    float* out = (float*)d_out;

    dim3 gq(128, 16, 3);
    qkv_kernel<<<gq, 128>>>(x, wq, bq, wk, bk, wv, bv);

    const int smem_attn = 256 * 72 * (int)sizeof(float);   // 73728
    cudaFuncSetAttribute(attn_kernel,
                         cudaFuncAttributeMaxDynamicSharedMemorySize, smem_attn);
    dim3 ga(16, 64);
    attn_kernel<<<ga, 256, smem_attn>>>(mask, out);
}